// round 9
// baseline (speedup 1.0000x reference)
#include <cuda_runtime.h>
#include <math.h>

#define NB      16          // batch rows
#define NSAMP   262144      // samples per row
#define NSTAGE  16          // biquads in the chain
#define TPB     128         // threads per block
#define LSUB    64          // samples per thread
#define CHUNK   (TPB*LSUB)  // 8192 samples per block
#define NCHUNK  (NSAMP/CHUNK) // 32 chunks per row
#define PAD     129         // smem transpose pad (conflict-free)

// libdevice intrinsics (exactly what XLA lowers jnp f32 transcendentals to;
// immune to any -use_fast_math remapping of sinf/cosf/expf/powf)
extern "C" {
    __device__ float __nv_sinf(float);
    __device__ float __nv_cosf(float);
    __device__ float __nv_expf(float);
    __device__ float __nv_powf(float, float);
    __device__ float __nv_sqrtf(float);
}

// ---- scratch (no allocations allowed; __device__ globals) ----
__device__ float   g_bufA[NB*NSAMP];
__device__ float   g_bufB[NB*NSAMP];
__device__ double4 g_cA[NSTAGE*NB];        // b0,b1,b2,a1 (f32-valued, stored fp64)
__device__ double  g_cB[NSTAGE*NB];        // a2
__device__ double4 g_Wd[NSTAGE*NB*8];      // T^(64*2^d), d=0..7 (fp64)
__device__ float   g_ginf[NB], g_goutf[NB];
__device__ double  g_agg[NSTAGE*NB*NCHUNK*2];   // block aggregates (fp64)
__device__ int     g_flag[NSTAGE*NB*NCHUNK];

// f32 constants exactly as XLA materializes the python f64 scalars
#define F_2PI      ((float)6.283185307179586)
#define F_FS       (96000.0f)
// _denorm_log constants: (float)log(lo), (float)(log(hi)-log(lo))
#define F_LOG_HPF_LO   ((float)2.995732273553991)   // log 20
#define F_LOG_HPF_D    ((float)3.2188758248682006)  // log 25
#define F_LOG_LPF_LO   ((float)8.517193191416238)   // log 5000
#define F_LOG_LPF_D    ((float)1.3862943611198906)  // log 4
#define F_LOG_SHF_LO   ((float)3.912023005428146)   // log 50
#define F_LOG_SHF_D    ((float)5.768320995793772)   // log 320
#define F_LOG_PK_LO    ((float)4.605170185988092)   // log 100
#define F_LOG_PK_D     ((float)5.010635294096256)   // log 150
#define F_LOG_Q_LO     ((float)-0.6931471805599453) // log 0.5
#define F_LOG_Q_D      ((float)3.4657359027997265)  // log 32

__device__ __forceinline__ float denorm_log_f(float n, float llo, float ld) {
    // exp(log_lo + n*(log_hi-log_lo)) — XLA eager op order, no fma
    return __nv_expf(__fadd_rn(llo, __fmul_rn(n, ld)));
}

// ---------------------------------------------------------------------------
// Kernel 0: coefficients computed in f32 bit-mimicking the JAX reference
// (op-for-op, left-assoc order, no fma, libdevice transcendentals).
// T-powers derived in fp64 FROM the f32-rounded normalized coefficients.
// ---------------------------------------------------------------------------
__global__ void coef_kernel(const float* __restrict__ params)
{
    int tid = threadIdx.x;
    if (tid >= NSTAGE*NB) return;
    int stage = tid >> 4;
    int row   = tid & 15;
    const float* p = params + row*50;
    float fn = p[stage*3+0];
    float gn = p[stage*3+1];
    float qn = p[stage*3+2];

    float Q  = denorm_log_f(qn, F_LOG_Q_LO, F_LOG_Q_D);
    // gain = -24 + gn*48
    float gdb = __fadd_rn(-24.0f, __fmul_rn(gn, 48.0f));

    float b0,b1,b2,a0,a1,a2;

    if (stage == 0) {                 // highpass
        float fc = denorm_log_f(fn, F_LOG_HPF_LO, F_LOG_HPF_D);
        float w0 = __fdiv_rn(__fmul_rn(F_2PI, fc), F_FS);
        float al = __fdiv_rn(__nv_sinf(w0), __fmul_rn(2.0f, Q));
        float c  = __nv_cosf(w0);
        float t  = __fadd_rn(1.0f, c);
        b0 = __fdiv_rn(t, 2.0f);
        b1 = -t;
        b2 = b0;
        a0 = __fadd_rn(1.0f, al);
        a1 = __fmul_rn(-2.0f, c);
        a2 = __fsub_rn(1.0f, al);
    } else if (stage == 15) {         // lowpass
        float fc = denorm_log_f(fn, F_LOG_LPF_LO, F_LOG_LPF_D);
        float w0 = __fdiv_rn(__fmul_rn(F_2PI, fc), F_FS);
        float al = __fdiv_rn(__nv_sinf(w0), __fmul_rn(2.0f, Q));
        float c  = __nv_cosf(w0);
        float t  = __fsub_rn(1.0f, c);
        b0 = __fdiv_rn(t, 2.0f);
        b1 = t;
        b2 = b0;
        a0 = __fadd_rn(1.0f, al);
        a1 = __fmul_rn(-2.0f, c);
        a2 = __fsub_rn(1.0f, al);
    } else if (stage == 1) {          // lowshelf
        float A  = __nv_powf(10.0f, __fdiv_rn(gdb, 40.0f));
        float fc = denorm_log_f(fn, F_LOG_SHF_LO, F_LOG_SHF_D);
        float w0 = __fdiv_rn(__fmul_rn(F_2PI, fc), F_FS);
        float al = __fdiv_rn(__nv_sinf(w0), __fmul_rn(2.0f, Q));
        float c  = __nv_cosf(w0);
        float sA = __nv_sqrtf(A);
        float ap1 = __fadd_rn(A, 1.0f);
        float am1 = __fsub_rn(A, 1.0f);
        float am1c = __fmul_rn(am1, c);
        float ap1c = __fmul_rn(ap1, c);
        float s2a  = __fmul_rn(__fmul_rn(2.0f, sA), al);
        // b0 = A*((A+1 - (A-1)*c) + 2sA*al)
        b0 = __fmul_rn(A, __fadd_rn(__fsub_rn(ap1, am1c), s2a));
        // b1 = (2*A)*((A-1) - (A+1)*c)
        b1 = __fmul_rn(__fmul_rn(2.0f, A), __fsub_rn(am1, ap1c));
        b2 = __fmul_rn(A, __fsub_rn(__fsub_rn(ap1, am1c), s2a));
        a0 = __fadd_rn(__fadd_rn(ap1, am1c), s2a);
        a1 = __fmul_rn(-2.0f, __fadd_rn(am1, ap1c));
        a2 = __fsub_rn(__fadd_rn(ap1, am1c), s2a);
    } else if (stage == 14) {         // highshelf
        float A  = __nv_powf(10.0f, __fdiv_rn(gdb, 40.0f));
        float fc = denorm_log_f(fn, F_LOG_SHF_LO, F_LOG_SHF_D);
        float w0 = __fdiv_rn(__fmul_rn(F_2PI, fc), F_FS);
        float al = __fdiv_rn(__nv_sinf(w0), __fmul_rn(2.0f, Q));
        float c  = __nv_cosf(w0);
        float sA = __nv_sqrtf(A);
        float ap1 = __fadd_rn(A, 1.0f);
        float am1 = __fsub_rn(A, 1.0f);
        float am1c = __fmul_rn(am1, c);
        float ap1c = __fmul_rn(ap1, c);
        float s2a  = __fmul_rn(__fmul_rn(2.0f, sA), al);
        b0 = __fmul_rn(A, __fadd_rn(__fadd_rn(ap1, am1c), s2a));
        // b1 = (-2*A)*((A-1) + (A+1)*c)
        b1 = __fmul_rn(__fmul_rn(-2.0f, A), __fadd_rn(am1, ap1c));
        b2 = __fmul_rn(A, __fsub_rn(__fadd_rn(ap1, am1c), s2a));
        a0 = __fadd_rn(__fsub_rn(ap1, am1c), s2a);
        a1 = __fmul_rn(2.0f, __fsub_rn(am1, ap1c));
        a2 = __fsub_rn(__fsub_rn(ap1, am1c), s2a);
    } else {                          // peak
        float A  = __nv_powf(10.0f, __fdiv_rn(gdb, 40.0f));
        float fc = denorm_log_f(fn, F_LOG_PK_LO, F_LOG_PK_D);
        float w0 = __fdiv_rn(__fmul_rn(F_2PI, fc), F_FS);
        float al = __fdiv_rn(__nv_sinf(w0), __fmul_rn(2.0f, Q));
        float c  = __nv_cosf(w0);
        float aA  = __fmul_rn(al, A);
        float adA = __fdiv_rn(al, A);
        b0 = __fadd_rn(1.0f, aA);
        b1 = __fmul_rn(-2.0f, c);
        b2 = __fsub_rn(1.0f, aA);
        a0 = __fadd_rn(1.0f, adA);
        a1 = __fmul_rn(-2.0f, c);
        a2 = __fsub_rn(1.0f, adA);
    }

    // normalize in f32 (reference: b0/a0 etc., f32 divisions)
    float nb0 = __fdiv_rn(b0, a0);
    float nb1 = __fdiv_rn(b1, a0);
    float nb2 = __fdiv_rn(b2, a0);
    float na1 = __fdiv_rn(a1, a0);
    float na2 = __fdiv_rn(a2, a0);

    double ib0=(double)nb0, ib1=(double)nb1, ib2=(double)nb2;
    double ia1=(double)na1, ia2=(double)na2;
    double4 cc; cc.x=ib0; cc.y=ib1; cc.z=ib2; cc.w=ia1;
    g_cA[tid] = cc;
    g_cB[tid] = ia2;

    // T = [[-a1,1],[-a2,0]]; store T^(64*2^d), d=0..7, fp64 squaring chain.
    double m00=-ia1, m01=1.0, m10=-ia2, m11=0.0;
    for (int k=0;k<6;k++){
        double n00 = m00*m00 + m01*m10, n01 = m00*m01 + m01*m11;
        double n10 = m10*m00 + m11*m10, n11 = m10*m01 + m11*m11;
        m00=n00;m01=n01;m10=n10;m11=n11;
    }
    for (int d=0;d<8;d++){
        double4 w; w.x=m00; w.y=m01; w.z=m10; w.w=m11;
        g_Wd[tid*8+d] = w;
        double n00 = m00*m00 + m01*m10, n01 = m00*m01 + m01*m11;
        double n10 = m10*m00 + m11*m10, n11 = m10*m01 + m11*m11;
        m00=n00;m01=n01;m10=n10;m11=n11;
    }
    for (int c=0;c<NCHUNK;c++) g_flag[tid*NCHUNK + c] = 0;
    if (stage == 0) {
        // in_db = -60 + p48*60 ; gain = 10**(in_db/20)  (all f32, powf)
        float indb  = __fadd_rn(-60.0f, __fmul_rn(p[48], 60.0f));
        float outdb = __fadd_rn(-60.0f, __fmul_rn(p[49], 60.0f));
        g_ginf[row]  = __nv_powf(10.0f, __fdiv_rn(indb, 20.0f));
        g_goutf[row] = __nv_powf(10.0f, __fdiv_rn(outdb, 20.0f));
    }
}

// ---------------------------------------------------------------------------
// Per-stage kernel: chunked scan with decoupled lookback. Recursion in fp64
// (exact given the f32-mimicked coefficients); inter-stage values rounded to
// f32 exactly as the reference's f32 arrays are.
// ---------------------------------------------------------------------------
__global__ void __launch_bounds__(TPB)
stage_kernel(int stage, const float* __restrict__ audio, float* __restrict__ out)
{
    __shared__ float   sx[LSUB*PAD];        // transposed sample tile (~33 KB)
    __shared__ double  sv1[TPB], sv2[TPB];  // per-thread scan states (fp64)
    __shared__ double4 sW[8];
    __shared__ double  sEntry[2];

    int bx    = blockIdx.x;
    int row   = bx & (NB-1);
    int chunk = bx >> 4;
    int t     = threadIdx.x;
    int rs    = stage*NB + row;

    const float* src; float* dst;
    if (stage == 0) src = audio; else src = (stage & 1) ? g_bufA : g_bufB;
    if (stage == 15) dst = out;  else dst = (stage & 1) ? g_bufB : g_bufA;

    if (t < 8) sW[t] = g_Wd[rs*8 + t];
    double4 c4 = g_cA[rs];
    double b0=c4.x, b1=c4.y, b2=c4.z, a1=c4.w;
    double a2c = g_cB[rs];

    size_t base = (size_t)row*NSAMP + (size_t)chunk*CHUNK;
    float ginf = (stage == 0) ? g_ginf[row] : 1.0f;

    // coalesced load (+ f32 input gain for stage 0, rounded like the ref)
    for (int k = t; k < CHUNK; k += TPB) {
        float x = src[base + k];
        if (stage == 0) x = __fmul_rn(x, ginf);
        sx[(k & (LSUB-1))*PAD + (k >> 6)] = x;
    }
    __syncthreads();

    // ---- pass 1: fp64 recursion from zero state ---------------------------
    double s1 = 0.0, s2 = 0.0;
    #pragma unroll 8
    for (int i = 0; i < LSUB; i++) {
        double x = (double)sx[i*PAD + t];
        double y = fma(b0, x, s1);
        s1 = fma(-a1, y, fma(b1, x, s2));
        s2 = fma(b2, x, -a2c*y);
    }
    double v1 = s1, v2 = s2;
    sv1[t] = v1; sv2[t] = v2;
    __syncthreads();

    // ---- intra-block affine Hillis-Steele scan in fp64 --------------------
    #pragma unroll
    for (int d = 0; d < 7; d++) {
        int o = 1 << d;
        double p1 = 0.0, p2 = 0.0;
        if (t >= o) { p1 = sv1[t-o]; p2 = sv2[t-o]; }
        __syncthreads();
        if (t >= o) {
            double4 W = sW[d];
            v1 = fma(W.x, p1, fma(W.y, p2, v1));
            v2 = fma(W.z, p1, fma(W.w, p2, v2));
            sv1[t] = v1; sv2[t] = v2;
        }
        __syncthreads();
    }

    // ---- publish block aggregate (inclusive of thread 127), fp64 ----------
    int aidx = rs*NCHUNK + chunk;
    if (t == TPB-1) {
        g_agg[2*aidx+0] = v1;
        g_agg[2*aidx+1] = v2;
        __threadfence();
        atomicExch(&g_flag[aidx], 1);
    }

    // ---- decoupled lookback (warp 0): fp64 Horner over predecessors -------
    if (t < 32) {
        double e1 = 0.0, e2 = 0.0;
        if (chunk > 0) {
            double a1v = 0.0, a2v = 0.0;
            if (t < chunk) {
                int idx = rs*NCHUNK + t;
                volatile int* fl = g_flag;
                while (fl[idx] == 0) __nanosleep(40);
                __threadfence();
                volatile double* ag = g_agg;
                a1v = ag[2*idx+0];
                a2v = ag[2*idx+1];
            }
            __syncwarp();
            double4 Tb = sW[7];                 // T^CHUNK (fp64)
            double acc1 = 0.0, acc2 = 0.0;      // S = sum Tb^{c-1-k} v_k
            for (int k = 0; k < chunk; k++) {
                double u1 = __shfl_sync(0xffffffffu, a1v, k);
                double u2 = __shfl_sync(0xffffffffu, a2v, k);
                double n1 = fma(Tb.x, acc1, fma(Tb.y, acc2, u1));
                double n2 = fma(Tb.z, acc1, fma(Tb.w, acc2, u2));
                acc1 = n1; acc2 = n2;
            }
            e1 = acc1; e2 = acc2;
        }
        if (t == 0) { sEntry[0] = e1; sEntry[1] = e2; }
    }
    __syncthreads();

    // ---- thread entry state: T^(64*t) * e_block + local excl. prefix ------
    double e1 = sEntry[0], e2 = sEntry[1];
    #pragma unroll
    for (int d = 0; d < 7; d++) {
        if (t & (1 << d)) {
            double4 W = sW[d];
            double n1 = fma(W.x, e1, W.y*e2);
            double n2 = fma(W.z, e1, W.w*e2);
            e1 = n1; e2 = n2;
        }
    }
    s1 = e1 + ((t > 0) ? sv1[t-1] : 0.0);
    s2 = e2 + ((t > 0) ? sv2[t-1] : 0.0);

    // ---- replay fp64 recursion with correct entry state, write y ----------
    float goutf = (stage == 15) ? g_goutf[row] : 1.0f;
    #pragma unroll 8
    for (int i = 0; i < LSUB; i++) {
        double x = (double)sx[i*PAD + t];
        double y = fma(b0, x, s1);
        s1 = fma(-a1, y, fma(b1, x, s2));
        s2 = fma(b2, x, -a2c*y);
        float yf = (float)y;
        if (stage == 15) yf = __fmul_rn(yf, goutf);
        sx[i*PAD + t] = yf;
    }
    __syncthreads();

    for (int k = t; k < CHUNK; k += TPB)
        dst[base + k] = sx[(k & (LSUB-1))*PAD + (k >> 6)];
}

// ---------------------------------------------------------------------------
extern "C" void kernel_launch(void* const* d_in, const int* in_sizes, int n_in,
                              void* d_out, int out_size)
{
    const float* audio  = (const float*)d_in[0];   // [16, 262144] f32
    const float* params = (const float*)d_in[1];   // [16, 50]     f32
    float* out = (float*)d_out;

    coef_kernel<<<1, NSTAGE*NB>>>(params);
    for (int s = 0; s < NSTAGE; s++)
        stage_kernel<<<NB*NCHUNK, TPB>>>(s, audio, out);
}

// round 10
// speedup vs baseline: 5.9121x; 5.9121x over previous
#include <cuda_runtime.h>
#include <math.h>

#define NB      16          // batch rows
#define NSAMP   262144      // samples per row
#define NSTAGE  16          // biquads in the chain
#define TPB     128         // threads per block
#define LSUB    64          // samples per thread
#define CHUNK   (TPB*LSUB)  // 8192 samples per block
#define NCHUNK  (NSAMP/CHUNK) // 32 chunks per row
#define PAD     129         // smem transpose pad (conflict-free)

// libdevice intrinsics (exactly what XLA lowers jnp f32 transcendentals to)
extern "C" {
    __device__ float __nv_sinf(float);
    __device__ float __nv_cosf(float);
    __device__ float __nv_expf(float);
    __device__ float __nv_powf(float, float);
    __device__ float __nv_sqrtf(float);
}

// ---- scratch (no allocations allowed; __device__ globals) ----
__device__ float   g_bufA[NB*NSAMP];
__device__ float   g_bufB[NB*NSAMP];
__device__ float4  g_cAf[NSTAGE*NB];       // b0,b1,b2,a1 (f32, JAX-mimicked)
__device__ float   g_cBf[NSTAGE*NB];       // a2 (f32)
__device__ double4 g_Wd[NSTAGE*NB*8];      // T^(64*2^d), d=0..7 (fp64)
__device__ float   g_ginf[NB], g_goutf[NB];
__device__ double  g_agg[NSTAGE*NB*NCHUNK*2];   // block aggregates (fp64)
__device__ int     g_flag[NSTAGE*NB*NCHUNK];

// f32 constants exactly as XLA materializes the python f64 scalars
#define F_2PI      ((float)6.283185307179586)
#define F_FS       (96000.0f)
#define F_LOG_HPF_LO   ((float)2.995732273553991)   // log 20
#define F_LOG_HPF_D    ((float)3.2188758248682006)  // log 25
#define F_LOG_LPF_LO   ((float)8.517193191416238)   // log 5000
#define F_LOG_LPF_D    ((float)1.3862943611198906)  // log 4
#define F_LOG_SHF_LO   ((float)3.912023005428146)   // log 50
#define F_LOG_SHF_D    ((float)5.768320995793772)   // log 320
#define F_LOG_PK_LO    ((float)4.605170185988092)   // log 100
#define F_LOG_PK_D     ((float)5.010635294096256)   // log 150
#define F_LOG_Q_LO     ((float)-0.6931471805599453) // log 0.5
#define F_LOG_Q_D      ((float)3.4657359027997265)  // log 32

__device__ __forceinline__ float denorm_log_f(float n, float llo, float ld) {
    return __nv_expf(__fadd_rn(llo, __fmul_rn(n, ld)));
}

// ---------------------------------------------------------------------------
// Kernel 0: coefficients in f32 bit-mimicking the JAX reference; T-powers in
// fp64 derived FROM the f32-rounded coefficients; flag reset per replay.
// ---------------------------------------------------------------------------
__global__ void coef_kernel(const float* __restrict__ params)
{
    int tid = threadIdx.x;
    if (tid >= NSTAGE*NB) return;
    int stage = tid >> 4;
    int row   = tid & 15;
    const float* p = params + row*50;
    float fn = p[stage*3+0];
    float gn = p[stage*3+1];
    float qn = p[stage*3+2];

    float Q   = denorm_log_f(qn, F_LOG_Q_LO, F_LOG_Q_D);
    float gdb = __fadd_rn(-24.0f, __fmul_rn(gn, 48.0f));

    float b0,b1,b2,a0,a1,a2;

    if (stage == 0) {                 // highpass
        float fc = denorm_log_f(fn, F_LOG_HPF_LO, F_LOG_HPF_D);
        float w0 = __fdiv_rn(__fmul_rn(F_2PI, fc), F_FS);
        float al = __fdiv_rn(__nv_sinf(w0), __fmul_rn(2.0f, Q));
        float c  = __nv_cosf(w0);
        float t  = __fadd_rn(1.0f, c);
        b0 = __fdiv_rn(t, 2.0f);
        b1 = -t;
        b2 = b0;
        a0 = __fadd_rn(1.0f, al);
        a1 = __fmul_rn(-2.0f, c);
        a2 = __fsub_rn(1.0f, al);
    } else if (stage == 15) {         // lowpass
        float fc = denorm_log_f(fn, F_LOG_LPF_LO, F_LOG_LPF_D);
        float w0 = __fdiv_rn(__fmul_rn(F_2PI, fc), F_FS);
        float al = __fdiv_rn(__nv_sinf(w0), __fmul_rn(2.0f, Q));
        float c  = __nv_cosf(w0);
        float t  = __fsub_rn(1.0f, c);
        b0 = __fdiv_rn(t, 2.0f);
        b1 = t;
        b2 = b0;
        a0 = __fadd_rn(1.0f, al);
        a1 = __fmul_rn(-2.0f, c);
        a2 = __fsub_rn(1.0f, al);
    } else if (stage == 1) {          // lowshelf
        float A  = __nv_powf(10.0f, __fdiv_rn(gdb, 40.0f));
        float fc = denorm_log_f(fn, F_LOG_SHF_LO, F_LOG_SHF_D);
        float w0 = __fdiv_rn(__fmul_rn(F_2PI, fc), F_FS);
        float al = __fdiv_rn(__nv_sinf(w0), __fmul_rn(2.0f, Q));
        float c  = __nv_cosf(w0);
        float sA = __nv_sqrtf(A);
        float ap1 = __fadd_rn(A, 1.0f);
        float am1 = __fsub_rn(A, 1.0f);
        float am1c = __fmul_rn(am1, c);
        float ap1c = __fmul_rn(ap1, c);
        float s2a  = __fmul_rn(__fmul_rn(2.0f, sA), al);
        b0 = __fmul_rn(A, __fadd_rn(__fsub_rn(ap1, am1c), s2a));
        b1 = __fmul_rn(__fmul_rn(2.0f, A), __fsub_rn(am1, ap1c));
        b2 = __fmul_rn(A, __fsub_rn(__fsub_rn(ap1, am1c), s2a));
        a0 = __fadd_rn(__fadd_rn(ap1, am1c), s2a);
        a1 = __fmul_rn(-2.0f, __fadd_rn(am1, ap1c));
        a2 = __fsub_rn(__fadd_rn(ap1, am1c), s2a);
    } else if (stage == 14) {         // highshelf
        float A  = __nv_powf(10.0f, __fdiv_rn(gdb, 40.0f));
        float fc = denorm_log_f(fn, F_LOG_SHF_LO, F_LOG_SHF_D);
        float w0 = __fdiv_rn(__fmul_rn(F_2PI, fc), F_FS);
        float al = __fdiv_rn(__nv_sinf(w0), __fmul_rn(2.0f, Q));
        float c  = __nv_cosf(w0);
        float sA = __nv_sqrtf(A);
        float ap1 = __fadd_rn(A, 1.0f);
        float am1 = __fsub_rn(A, 1.0f);
        float am1c = __fmul_rn(am1, c);
        float ap1c = __fmul_rn(ap1, c);
        float s2a  = __fmul_rn(__fmul_rn(2.0f, sA), al);
        b0 = __fmul_rn(A, __fadd_rn(__fadd_rn(ap1, am1c), s2a));
        b1 = __fmul_rn(__fmul_rn(-2.0f, A), __fadd_rn(am1, ap1c));
        b2 = __fmul_rn(A, __fsub_rn(__fadd_rn(ap1, am1c), s2a));
        a0 = __fadd_rn(__fsub_rn(ap1, am1c), s2a);
        a1 = __fmul_rn(2.0f, __fsub_rn(am1, ap1c));
        a2 = __fsub_rn(__fsub_rn(ap1, am1c), s2a);
    } else {                          // peak
        float A  = __nv_powf(10.0f, __fdiv_rn(gdb, 40.0f));
        float fc = denorm_log_f(fn, F_LOG_PK_LO, F_LOG_PK_D);
        float w0 = __fdiv_rn(__fmul_rn(F_2PI, fc), F_FS);
        float al = __fdiv_rn(__nv_sinf(w0), __fmul_rn(2.0f, Q));
        float c  = __nv_cosf(w0);
        float aA  = __fmul_rn(al, A);
        float adA = __fdiv_rn(al, A);
        b0 = __fadd_rn(1.0f, aA);
        b1 = __fmul_rn(-2.0f, c);
        b2 = __fsub_rn(1.0f, aA);
        a0 = __fadd_rn(1.0f, adA);
        a1 = __fmul_rn(-2.0f, c);
        a2 = __fsub_rn(1.0f, adA);
    }

    float nb0 = __fdiv_rn(b0, a0);
    float nb1 = __fdiv_rn(b1, a0);
    float nb2 = __fdiv_rn(b2, a0);
    float na1 = __fdiv_rn(a1, a0);
    float na2 = __fdiv_rn(a2, a0);

    g_cAf[tid] = make_float4(nb0, nb1, nb2, na1);
    g_cBf[tid] = na2;

    // T = [[-a1,1],[-a2,0]] from the f32 coefficients; powers in fp64.
    double ia1=(double)na1, ia2=(double)na2;
    double m00=-ia1, m01=1.0, m10=-ia2, m11=0.0;
    for (int k=0;k<6;k++){
        double n00 = m00*m00 + m01*m10, n01 = m00*m01 + m01*m11;
        double n10 = m10*m00 + m11*m10, n11 = m10*m01 + m11*m11;
        m00=n00;m01=n01;m10=n10;m11=n11;
    }
    for (int d=0;d<8;d++){
        double4 w; w.x=m00; w.y=m01; w.z=m10; w.w=m11;
        g_Wd[tid*8+d] = w;
        double n00 = m00*m00 + m01*m10, n01 = m00*m01 + m01*m11;
        double n10 = m10*m00 + m11*m10, n11 = m10*m01 + m11*m11;
        m00=n00;m01=n01;m10=n10;m11=n11;
    }
    for (int c=0;c<NCHUNK;c++) g_flag[tid*NCHUNK + c] = 0;
    if (stage == 0) {
        float indb  = __fadd_rn(-60.0f, __fmul_rn(p[48], 60.0f));
        float outdb = __fadd_rn(-60.0f, __fmul_rn(p[49], 60.0f));
        g_ginf[row]  = __nv_powf(10.0f, __fdiv_rn(indb, 20.0f));
        g_goutf[row] = __nv_powf(10.0f, __fdiv_rn(outdb, 20.0f));
    }
}

// ---------------------------------------------------------------------------
// Per-stage kernel: fp32 pass-1/replay (4-cyc FFMA chains instead of ~50-cyc
// DFMA), fp64 scan + lookback + entry-state propagation (cheap, exact).
// ---------------------------------------------------------------------------
__global__ void __launch_bounds__(TPB)
stage_kernel(int stage, const float* __restrict__ audio, float* __restrict__ out)
{
    __shared__ float   sx[LSUB*PAD];        // transposed sample tile (~33 KB)
    __shared__ double  sv1[TPB], sv2[TPB];  // per-thread scan states (fp64)
    __shared__ double4 sW[8];
    __shared__ double  sEntry[2];

    int bx    = blockIdx.x;
    int row   = bx & (NB-1);
    int chunk = bx >> 4;
    int t     = threadIdx.x;
    int rs    = stage*NB + row;

    const float* src; float* dst;
    if (stage == 0) src = audio; else src = (stage & 1) ? g_bufA : g_bufB;
    if (stage == 15) dst = out;  else dst = (stage & 1) ? g_bufB : g_bufA;

    if (t < 8) sW[t] = g_Wd[rs*8 + t];
    float4 c4 = g_cAf[rs];
    float b0=c4.x, b1=c4.y, b2=c4.z, a1=c4.w;
    float a2c = g_cBf[rs];

    size_t base = (size_t)row*NSAMP + (size_t)chunk*CHUNK;
    float ginf = (stage == 0) ? g_ginf[row] : 1.0f;

    // coalesced load (+ f32 input gain for stage 0, rounded like the ref)
    for (int k = t; k < CHUNK; k += TPB) {
        float x = src[base + k];
        if (stage == 0) x = __fmul_rn(x, ginf);
        sx[(k & (LSUB-1))*PAD + (k >> 6)] = x;
    }
    __syncthreads();

    // ---- pass 1: fp32 recursion from zero state ---------------------------
    float s1 = 0.f, s2 = 0.f;
    #pragma unroll 8
    for (int i = 0; i < LSUB; i++) {
        float x = sx[i*PAD + t];
        float y = fmaf(b0, x, s1);
        s1 = fmaf(-a1, y, fmaf(b1, x, s2));
        s2 = fmaf(b2, x, -a2c*y);
    }
    double v1 = (double)s1, v2 = (double)s2;
    sv1[t] = v1; sv2[t] = v2;
    __syncthreads();

    // ---- intra-block affine Hillis-Steele scan in fp64 --------------------
    #pragma unroll
    for (int d = 0; d < 7; d++) {
        int o = 1 << d;
        double p1 = 0.0, p2 = 0.0;
        if (t >= o) { p1 = sv1[t-o]; p2 = sv2[t-o]; }
        __syncthreads();
        if (t >= o) {
            double4 W = sW[d];
            v1 = fma(W.x, p1, fma(W.y, p2, v1));
            v2 = fma(W.z, p1, fma(W.w, p2, v2));
            sv1[t] = v1; sv2[t] = v2;
        }
        __syncthreads();
    }

    // ---- publish block aggregate (inclusive of thread 127), fp64 ----------
    int aidx = rs*NCHUNK + chunk;
    if (t == TPB-1) {
        g_agg[2*aidx+0] = v1;
        g_agg[2*aidx+1] = v2;
        __threadfence();
        atomicExch(&g_flag[aidx], 1);
    }

    // ---- decoupled lookback (warp 0): fp64 Horner over predecessors -------
    if (t < 32) {
        double e1 = 0.0, e2 = 0.0;
        if (chunk > 0) {
            double a1v = 0.0, a2v = 0.0;
            if (t < chunk) {
                int idx = rs*NCHUNK + t;
                volatile int* fl = g_flag;
                while (fl[idx] == 0) __nanosleep(40);
                __threadfence();
                volatile double* ag = g_agg;
                a1v = ag[2*idx+0];
                a2v = ag[2*idx+1];
            }
            __syncwarp();
            double4 Tb = sW[7];                 // T^CHUNK (fp64)
            double acc1 = 0.0, acc2 = 0.0;      // S = sum Tb^{c-1-k} v_k
            for (int k = 0; k < chunk; k++) {
                double u1 = __shfl_sync(0xffffffffu, a1v, k);
                double u2 = __shfl_sync(0xffffffffu, a2v, k);
                double n1 = fma(Tb.x, acc1, fma(Tb.y, acc2, u1));
                double n2 = fma(Tb.z, acc1, fma(Tb.w, acc2, u2));
                acc1 = n1; acc2 = n2;
            }
            e1 = acc1; e2 = acc2;
        }
        if (t == 0) { sEntry[0] = e1; sEntry[1] = e2; }
    }
    __syncthreads();

    // ---- thread entry state: T^(64*t) * e_block + local excl. prefix ------
    double e1 = sEntry[0], e2 = sEntry[1];
    #pragma unroll
    for (int d = 0; d < 7; d++) {
        if (t & (1 << d)) {
            double4 W = sW[d];
            double n1 = fma(W.x, e1, W.y*e2);
            double n2 = fma(W.z, e1, W.w*e2);
            e1 = n1; e2 = n2;
        }
    }
    s1 = (float)(e1 + ((t > 0) ? sv1[t-1] : 0.0));
    s2 = (float)(e2 + ((t > 0) ? sv2[t-1] : 0.0));

    // ---- replay fp32 recursion with correct entry state, write y ----------
    float goutf = (stage == 15) ? g_goutf[row] : 1.0f;
    #pragma unroll 8
    for (int i = 0; i < LSUB; i++) {
        float x = sx[i*PAD + t];
        float y = fmaf(b0, x, s1);
        s1 = fmaf(-a1, y, fmaf(b1, x, s2));
        s2 = fmaf(b2, x, -a2c*y);
        if (stage == 15) y = __fmul_rn(y, goutf);
        sx[i*PAD + t] = y;
    }
    __syncthreads();

    for (int k = t; k < CHUNK; k += TPB)
        dst[base + k] = sx[(k & (LSUB-1))*PAD + (k >> 6)];
}

// ---------------------------------------------------------------------------
extern "C" void kernel_launch(void* const* d_in, const int* in_sizes, int n_in,
                              void* d_out, int out_size)
{
    const float* audio  = (const float*)d_in[0];   // [16, 262144] f32
    const float* params = (const float*)d_in[1];   // [16, 50]     f32
    float* out = (float*)d_out;

    coef_kernel<<<1, NSTAGE*NB>>>(params);
    for (int s = 0; s < NSTAGE; s++)
        stage_kernel<<<NB*NCHUNK, TPB>>>(s, audio, out);
}

// round 11
// speedup vs baseline: 8.6443x; 1.4621x over previous
#include <cuda_runtime.h>
#include <math.h>

#define NB      16          // batch rows
#define NSAMP   262144      // samples per row
#define NSTAGE  16          // biquads in the chain
#define TPB     128         // threads per block
#define LSUB    64          // samples per thread
#define CHUNK   (TPB*LSUB)  // 8192 samples per block
#define NCHUNK  (NSAMP/CHUNK) // 32 chunks per row
#define PAD     129         // smem transpose pad (conflict-free)

// libdevice intrinsics (exactly what XLA lowers jnp f32 transcendentals to)
extern "C" {
    __device__ float __nv_sinf(float);
    __device__ float __nv_cosf(float);
    __device__ float __nv_expf(float);
    __device__ float __nv_powf(float, float);
    __device__ float __nv_sqrtf(float);
}

// ---- scratch (no allocations allowed; __device__ globals) ----
__device__ float4  g_cAf[NSTAGE*NB];       // b0,b1,b2,a1 (f32, JAX-mimicked)
__device__ float   g_cBf[NSTAGE*NB];       // a2 (f32)
__device__ double4 g_Wd[NSTAGE*NB*8];      // T^(64*2^d), d=0..7 (fp64)
__device__ float   g_ginf[NB], g_goutf[NB];
__device__ double  g_agg[NSTAGE*NB*NCHUNK*2];   // block aggregates (fp64)
__device__ int     g_flag[NSTAGE*NB*NCHUNK];

// f32 constants exactly as XLA materializes the python f64 scalars
#define F_2PI      ((float)6.283185307179586)
#define F_FS       (96000.0f)
#define F_LOG_HPF_LO   ((float)2.995732273553991)   // log 20
#define F_LOG_HPF_D    ((float)3.2188758248682006)  // log 25
#define F_LOG_LPF_LO   ((float)8.517193191416238)   // log 5000
#define F_LOG_LPF_D    ((float)1.3862943611198906)  // log 4
#define F_LOG_SHF_LO   ((float)3.912023005428146)   // log 50
#define F_LOG_SHF_D    ((float)5.768320995793772)   // log 320
#define F_LOG_PK_LO    ((float)4.605170185988092)   // log 100
#define F_LOG_PK_D     ((float)5.010635294096256)   // log 150
#define F_LOG_Q_LO     ((float)-0.6931471805599453) // log 0.5
#define F_LOG_Q_D      ((float)3.4657359027997265)  // log 32

__device__ __forceinline__ float denorm_log_f(float n, float llo, float ld) {
    return __nv_expf(__fadd_rn(llo, __fmul_rn(n, ld)));
}

// ---------------------------------------------------------------------------
// Kernel 0: coefficients in f32 bit-mimicking the JAX reference; T-powers in
// fp64 derived FROM the f32-rounded coefficients; flag reset per replay.
// ---------------------------------------------------------------------------
__global__ void coef_kernel(const float* __restrict__ params)
{
    int tid = threadIdx.x;
    if (tid >= NSTAGE*NB) return;
    int stage = tid >> 4;
    int row   = tid & 15;
    const float* p = params + row*50;
    float fn = p[stage*3+0];
    float gn = p[stage*3+1];
    float qn = p[stage*3+2];

    float Q   = denorm_log_f(qn, F_LOG_Q_LO, F_LOG_Q_D);
    float gdb = __fadd_rn(-24.0f, __fmul_rn(gn, 48.0f));

    float b0,b1,b2,a0,a1,a2;

    if (stage == 0) {                 // highpass
        float fc = denorm_log_f(fn, F_LOG_HPF_LO, F_LOG_HPF_D);
        float w0 = __fdiv_rn(__fmul_rn(F_2PI, fc), F_FS);
        float al = __fdiv_rn(__nv_sinf(w0), __fmul_rn(2.0f, Q));
        float c  = __nv_cosf(w0);
        float t  = __fadd_rn(1.0f, c);
        b0 = __fdiv_rn(t, 2.0f);
        b1 = -t;
        b2 = b0;
        a0 = __fadd_rn(1.0f, al);
        a1 = __fmul_rn(-2.0f, c);
        a2 = __fsub_rn(1.0f, al);
    } else if (stage == 15) {         // lowpass
        float fc = denorm_log_f(fn, F_LOG_LPF_LO, F_LOG_LPF_D);
        float w0 = __fdiv_rn(__fmul_rn(F_2PI, fc), F_FS);
        float al = __fdiv_rn(__nv_sinf(w0), __fmul_rn(2.0f, Q));
        float c  = __nv_cosf(w0);
        float t  = __fsub_rn(1.0f, c);
        b0 = __fdiv_rn(t, 2.0f);
        b1 = t;
        b2 = b0;
        a0 = __fadd_rn(1.0f, al);
        a1 = __fmul_rn(-2.0f, c);
        a2 = __fsub_rn(1.0f, al);
    } else if (stage == 1) {          // lowshelf
        float A  = __nv_powf(10.0f, __fdiv_rn(gdb, 40.0f));
        float fc = denorm_log_f(fn, F_LOG_SHF_LO, F_LOG_SHF_D);
        float w0 = __fdiv_rn(__fmul_rn(F_2PI, fc), F_FS);
        float al = __fdiv_rn(__nv_sinf(w0), __fmul_rn(2.0f, Q));
        float c  = __nv_cosf(w0);
        float sA = __nv_sqrtf(A);
        float ap1 = __fadd_rn(A, 1.0f);
        float am1 = __fsub_rn(A, 1.0f);
        float am1c = __fmul_rn(am1, c);
        float ap1c = __fmul_rn(ap1, c);
        float s2a  = __fmul_rn(__fmul_rn(2.0f, sA), al);
        b0 = __fmul_rn(A, __fadd_rn(__fsub_rn(ap1, am1c), s2a));
        b1 = __fmul_rn(__fmul_rn(2.0f, A), __fsub_rn(am1, ap1c));
        b2 = __fmul_rn(A, __fsub_rn(__fsub_rn(ap1, am1c), s2a));
        a0 = __fadd_rn(__fadd_rn(ap1, am1c), s2a);
        a1 = __fmul_rn(-2.0f, __fadd_rn(am1, ap1c));
        a2 = __fsub_rn(__fadd_rn(ap1, am1c), s2a);
    } else if (stage == 14) {         // highshelf
        float A  = __nv_powf(10.0f, __fdiv_rn(gdb, 40.0f));
        float fc = denorm_log_f(fn, F_LOG_SHF_LO, F_LOG_SHF_D);
        float w0 = __fdiv_rn(__fmul_rn(F_2PI, fc), F_FS);
        float al = __fdiv_rn(__nv_sinf(w0), __fmul_rn(2.0f, Q));
        float c  = __nv_cosf(w0);
        float sA = __nv_sqrtf(A);
        float ap1 = __fadd_rn(A, 1.0f);
        float am1 = __fsub_rn(A, 1.0f);
        float am1c = __fmul_rn(am1, c);
        float ap1c = __fmul_rn(ap1, c);
        float s2a  = __fmul_rn(__fmul_rn(2.0f, sA), al);
        b0 = __fmul_rn(A, __fadd_rn(__fadd_rn(ap1, am1c), s2a));
        b1 = __fmul_rn(__fmul_rn(-2.0f, A), __fadd_rn(am1, ap1c));
        b2 = __fmul_rn(A, __fsub_rn(__fadd_rn(ap1, am1c), s2a));
        a0 = __fadd_rn(__fsub_rn(ap1, am1c), s2a);
        a1 = __fmul_rn(2.0f, __fsub_rn(am1, ap1c));
        a2 = __fsub_rn(__fsub_rn(ap1, am1c), s2a);
    } else {                          // peak
        float A  = __nv_powf(10.0f, __fdiv_rn(gdb, 40.0f));
        float fc = denorm_log_f(fn, F_LOG_PK_LO, F_LOG_PK_D);
        float w0 = __fdiv_rn(__fmul_rn(F_2PI, fc), F_FS);
        float al = __fdiv_rn(__nv_sinf(w0), __fmul_rn(2.0f, Q));
        float c  = __nv_cosf(w0);
        float aA  = __fmul_rn(al, A);
        float adA = __fdiv_rn(al, A);
        b0 = __fadd_rn(1.0f, aA);
        b1 = __fmul_rn(-2.0f, c);
        b2 = __fsub_rn(1.0f, aA);
        a0 = __fadd_rn(1.0f, adA);
        a1 = __fmul_rn(-2.0f, c);
        a2 = __fsub_rn(1.0f, adA);
    }

    float nb0 = __fdiv_rn(b0, a0);
    float nb1 = __fdiv_rn(b1, a0);
    float nb2 = __fdiv_rn(b2, a0);
    float na1 = __fdiv_rn(a1, a0);
    float na2 = __fdiv_rn(a2, a0);

    g_cAf[tid] = make_float4(nb0, nb1, nb2, na1);
    g_cBf[tid] = na2;

    // T = [[-a1,1],[-a2,0]] from the f32 coefficients; powers in fp64.
    double ia1=(double)na1, ia2=(double)na2;
    double m00=-ia1, m01=1.0, m10=-ia2, m11=0.0;
    for (int k=0;k<6;k++){
        double n00 = m00*m00 + m01*m10, n01 = m00*m01 + m01*m11;
        double n10 = m10*m00 + m11*m10, n11 = m10*m01 + m11*m11;
        m00=n00;m01=n01;m10=n10;m11=n11;
    }
    for (int d=0;d<8;d++){
        double4 w; w.x=m00; w.y=m01; w.z=m10; w.w=m11;
        g_Wd[tid*8+d] = w;
        double n00 = m00*m00 + m01*m10, n01 = m00*m01 + m01*m11;
        double n10 = m10*m00 + m11*m10, n11 = m10*m01 + m11*m11;
        m00=n00;m01=n01;m10=n10;m11=n11;
    }
    for (int c=0;c<NCHUNK;c++) g_flag[tid*NCHUNK + c] = 0;
    if (stage == 0) {
        float indb  = __fadd_rn(-60.0f, __fmul_rn(p[48], 60.0f));
        float outdb = __fadd_rn(-60.0f, __fmul_rn(p[49], 60.0f));
        g_ginf[row]  = __nv_powf(10.0f, __fdiv_rn(indb, 20.0f));
        g_goutf[row] = __nv_powf(10.0f, __fdiv_rn(outdb, 20.0f));
    }
}

// ---------------------------------------------------------------------------
// Fused kernel: each block keeps its 8192-sample tile in smem across ALL 16
// stages. The only cross-block traffic is the 16-byte lookback aggregate per
// (stage, chunk). All 512 blocks are co-resident (35 KB smem, 52 regs) and
// lookback only waits on lower block indices => no deadlock either way.
// Arithmetic is bit-identical to the per-stage version.
// ---------------------------------------------------------------------------
__global__ void __launch_bounds__(TPB)
fused_kernel(const float* __restrict__ audio, float* __restrict__ out)
{
    __shared__ float   sx[LSUB*PAD];        // resident sample tile (~33 KB)
    __shared__ double  sv1[TPB], sv2[TPB];  // per-thread scan states (fp64)
    __shared__ double4 sW[8];
    __shared__ double  sEntry[2];

    int bx    = blockIdx.x;
    int row   = bx & (NB-1);
    int chunk = bx >> 4;
    int t     = threadIdx.x;

    size_t base = (size_t)row*NSAMP + (size_t)chunk*CHUNK;
    float ginf = g_ginf[row];
    float goutf = g_goutf[row];

    // one-time coalesced load + transpose, with f32 input gain (as reference)
    for (int k = t; k < CHUNK; k += TPB) {
        float x = __fmul_rn(audio[base + k], ginf);
        sx[(k & (LSUB-1))*PAD + (k >> 6)] = x;
    }

    for (int stage = 0; stage < NSTAGE; stage++) {
        int rs = stage*NB + row;

        // sync: sx writes (load/replay) + sW free for overwrite
        __syncthreads();
        if (t < 8) sW[t] = g_Wd[rs*8 + t];
        float4 c4 = g_cAf[rs];
        float b0=c4.x, b1=c4.y, b2=c4.z, a1=c4.w;
        float a2c = g_cBf[rs];
        __syncthreads();

        // ---- pass 1: fp32 recursion from zero state (own smem column) -----
        float s1 = 0.f, s2 = 0.f;
        #pragma unroll 8
        for (int i = 0; i < LSUB; i++) {
            float x = sx[i*PAD + t];
            float y = fmaf(b0, x, s1);
            s1 = fmaf(-a1, y, fmaf(b1, x, s2));
            s2 = fmaf(b2, x, -a2c*y);
        }
        double v1 = (double)s1, v2 = (double)s2;
        sv1[t] = v1; sv2[t] = v2;
        __syncthreads();

        // ---- intra-block affine Hillis-Steele scan in fp64 ----------------
        #pragma unroll
        for (int d = 0; d < 7; d++) {
            int o = 1 << d;
            double p1 = 0.0, p2 = 0.0;
            if (t >= o) { p1 = sv1[t-o]; p2 = sv2[t-o]; }
            __syncthreads();
            if (t >= o) {
                double4 W = sW[d];
                v1 = fma(W.x, p1, fma(W.y, p2, v1));
                v2 = fma(W.z, p1, fma(W.w, p2, v2));
                sv1[t] = v1; sv2[t] = v2;
            }
            __syncthreads();
        }

        // ---- publish block aggregate for this stage -----------------------
        int aidx = rs*NCHUNK + chunk;
        if (t == TPB-1) {
            g_agg[2*aidx+0] = v1;
            g_agg[2*aidx+1] = v2;
            __threadfence();
            atomicExch(&g_flag[aidx], 1);
        }

        // ---- decoupled lookback (warp 0): fp64 Horner over predecessors ---
        if (t < 32) {
            double e1 = 0.0, e2 = 0.0;
            if (chunk > 0) {
                double a1v = 0.0, a2v = 0.0;
                if (t < chunk) {
                    int idx = rs*NCHUNK + t;
                    volatile int* fl = g_flag;
                    while (fl[idx] == 0) __nanosleep(40);
                    __threadfence();
                    volatile double* ag = g_agg;
                    a1v = ag[2*idx+0];
                    a2v = ag[2*idx+1];
                }
                __syncwarp();
                double4 Tb = sW[7];                 // T^CHUNK (fp64)
                double acc1 = 0.0, acc2 = 0.0;      // S = sum Tb^{c-1-k} v_k
                for (int k = 0; k < chunk; k++) {
                    double u1 = __shfl_sync(0xffffffffu, a1v, k);
                    double u2 = __shfl_sync(0xffffffffu, a2v, k);
                    double n1 = fma(Tb.x, acc1, fma(Tb.y, acc2, u1));
                    double n2 = fma(Tb.z, acc1, fma(Tb.w, acc2, u2));
                    acc1 = n1; acc2 = n2;
                }
                e1 = acc1; e2 = acc2;
            }
            if (t == 0) { sEntry[0] = e1; sEntry[1] = e2; }
        }
        __syncthreads();

        // ---- thread entry state: T^(64*t) * e_block + local excl. prefix --
        double e1 = sEntry[0], e2 = sEntry[1];
        #pragma unroll
        for (int d = 0; d < 7; d++) {
            if (t & (1 << d)) {
                double4 W = sW[d];
                double n1 = fma(W.x, e1, W.y*e2);
                double n2 = fma(W.z, e1, W.w*e2);
                e1 = n1; e2 = n2;
            }
        }
        s1 = (float)(e1 + ((t > 0) ? sv1[t-1] : 0.0));
        s2 = (float)(e2 + ((t > 0) ? sv2[t-1] : 0.0));

        // ---- replay fp32 recursion, write y back into own smem column -----
        #pragma unroll 8
        for (int i = 0; i < LSUB; i++) {
            float x = sx[i*PAD + t];
            float y = fmaf(b0, x, s1);
            s1 = fmaf(-a1, y, fmaf(b1, x, s2));
            s2 = fmaf(b2, x, -a2c*y);
            if (stage == NSTAGE-1) y = __fmul_rn(y, goutf);
            sx[i*PAD + t] = y;
        }
        // loop-top __syncthreads() orders replay writes vs next stage
    }

    __syncthreads();
    // one-time coalesced store
    for (int k = t; k < CHUNK; k += TPB)
        out[base + k] = sx[(k & (LSUB-1))*PAD + (k >> 6)];
}

// ---------------------------------------------------------------------------
extern "C" void kernel_launch(void* const* d_in, const int* in_sizes, int n_in,
                              void* d_out, int out_size)
{
    const float* audio  = (const float*)d_in[0];   // [16, 262144] f32
    const float* params = (const float*)d_in[1];   // [16, 50]     f32
    float* out = (float*)d_out;

    coef_kernel<<<1, NSTAGE*NB>>>(params);
    fused_kernel<<<NB*NCHUNK, TPB>>>(audio, out);
}